// round 8
// baseline (speedup 1.0000x reference)
#include <cuda_runtime.h>
#include <cstdint>

// out[b,l,d] = sum_c code[b,l,c] * W[l,c,d]
// code: [256, 64, 256] f32,  W: [64, 256, 1024] f32,  out: [256, 64, 1024] f32
// Per l: A[M=256,K=256] (row stride 16384) x B[K=256,N=1024] -> [M,N]
// tf32 mma.sync GEMM (base sm_103 ISA — tcgen05 is not compilable in this
// harness: it lowers via compute_103 without the 'a' feature suffix).
// CTA 128x128, BK=32, 8 warps (2M x 4N), warp tile 64x32, m16n8k8 tf32.

static constexpr int Ldim = 64, Cdim = 256, Ddim = 1024;
static constexpr int BM = 128, BN = 128, BK = 32;
static constexpr int NCH = Cdim / BK;                 // 8
static constexpr int SMEM_TOTAL = 2 * (BM * BK + BN * BK) * 4;   // 65536

__device__ __forceinline__ uint32_t swz(uint32_t o) { return o ^ ((o >> 3) & 0x70); }
__device__ __forceinline__ uint32_t smem_u32(const void* p) {
    uint32_t a;
    asm("{ .reg .u64 t; cvta.to.shared.u64 t, %1; cvt.u32.u64 %0, t; }" : "=r"(a) : "l"(p));
    return a;
}
__device__ __forceinline__ uint32_t f2tf(float f) {
    uint32_t r;
    asm("cvt.rna.tf32.f32 %0, %1;" : "=r"(r) : "f"(f));
    return r;
}
__device__ __forceinline__ void sts128(uint32_t addr, uint32_t x, uint32_t y,
                                       uint32_t z, uint32_t w) {
    asm volatile("st.shared.v4.b32 [%0], {%1, %2, %3, %4};"
                 :: "r"(addr), "r"(x), "r"(y), "r"(z), "r"(w) : "memory");
}
__device__ __forceinline__ void ldsm4(uint32_t addr, uint32_t& r0, uint32_t& r1,
                                      uint32_t& r2, uint32_t& r3) {
    asm volatile("ldmatrix.sync.aligned.m8n8.x4.shared.b16 {%0, %1, %2, %3}, [%4];"
                 : "=r"(r0), "=r"(r1), "=r"(r2), "=r"(r3) : "r"(addr));
}
__device__ __forceinline__ void mma_tf32(float& c0, float& c1, float& c2, float& c3,
                                         uint32_t a0, uint32_t a1, uint32_t a2, uint32_t a3,
                                         uint32_t b0, uint32_t b1) {
    asm volatile(
        "mma.sync.aligned.m16n8k8.row.col.f32.tf32.tf32.f32 "
        "{%0, %1, %2, %3}, {%4, %5, %6, %7}, {%8, %9}, {%0, %1, %2, %3};"
        : "+f"(c0), "+f"(c1), "+f"(c2), "+f"(c3)
        : "r"(a0), "r"(a1), "r"(a2), "r"(a3), "r"(b0), "r"(b1));
}

extern "C" __global__ void __launch_bounds__(256, 1)
grouped_gemm_tf32(const float* __restrict__ code,
                  const float* __restrict__ W,
                  float* __restrict__ out) {
    extern __shared__ char smem[];
    const uint32_t sbase = smem_u32(smem);

    const int tid  = threadIdx.x;
    const int lane = tid & 31;
    const int wid  = tid >> 5;
    const int l  = blockIdx.z;
    const int m0 = blockIdx.y * BM;
    const int n0 = blockIdx.x * BN;

    const int mw = (wid >> 2) * 64;    // warp M offset within CTA tile
    const int nw = (wid & 3) * 32;     // warp N offset
    const int q  = lane >> 3;          // ldmatrix quadrant
    const int r  = lane & 7;
    const int g  = lane >> 2;          // mma group id
    const int tg = lane & 3;           // thread in group

    // Global-load assignments
    const int arow = tid >> 1;                 // 0..127  (M row)
    const int acol = (tid & 1) * 16;           // k offset (16 floats per thread)
    const int bn   = tid & 127;                // N column
    const int bk   = (tid >> 7) * 16;          // k offset (16 rows per thread)

    const float* Ag = code + (size_t)l * Cdim
                      + (size_t)(m0 + arow) * (Ldim * Cdim) + acol;
    const float* Bg = W + (size_t)l * Cdim * Ddim + (size_t)bk * Ddim + n0 + bn;

    float c[4][4][4];
    #pragma unroll
    for (int i = 0; i < 4; i++)
        #pragma unroll
        for (int j = 0; j < 4; j++)
            #pragma unroll
            for (int k = 0; k < 4; k++)
                c[i][j][k] = 0.f;

    float4 as[4];
    float  bs[16];

    // ---- prologue: load chunk 0 ----
    #pragma unroll
    for (int j = 0; j < 4; j++) as[j] = *(const float4*)(Ag + 4 * j);
    #pragma unroll
    for (int j = 0; j < 16; j++) bs[j] = Bg[(size_t)j * Ddim];

    // store chunk into buffer `buf` with fp32->tf32 rounding
    auto store_chunk = [&](int buf) {
        const uint32_t ab = sbase + buf * ((BM + BN) * BK * 4);
        const uint32_t bb = ab + BM * BK * 4;
        #pragma unroll
        for (int j = 0; j < 4; j++) {
            uint32_t o = swz((uint32_t)(arow * 128 + (acol + 4 * j) * 4));
            sts128(ab + o, f2tf(as[j].x), f2tf(as[j].y), f2tf(as[j].z), f2tf(as[j].w));
        }
        #pragma unroll
        for (int jj = 0; jj < 4; jj++) {
            uint32_t o = swz((uint32_t)(bn * 128 + (bk + 4 * jj) * 4));
            sts128(bb + o, f2tf(bs[4 * jj + 0]), f2tf(bs[4 * jj + 1]),
                           f2tf(bs[4 * jj + 2]), f2tf(bs[4 * jj + 3]));
        }
    };

    store_chunk(0);
    __syncthreads();

    for (int ch = 0; ch < NCH; ++ch) {
        const int buf = ch & 1;

        // prefetch next chunk's globals into registers (overlaps with mma)
        if (ch + 1 < NCH) {
            const float* Agn = Ag + (ch + 1) * BK;
            const float* Bgn = Bg + (size_t)(ch + 1) * BK * Ddim;
            #pragma unroll
            for (int j = 0; j < 4; j++) as[j] = *(const float4*)(Agn + 4 * j);
            #pragma unroll
            for (int j = 0; j < 16; j++) bs[j] = Bgn[(size_t)j * Ddim];
        }

        // ---- compute this chunk ----
        const uint32_t ab = sbase + buf * ((BM + BN) * BK * 4);
        const uint32_t bb = ab + BM * BK * 4;
        #pragma unroll
        for (int k8 = 0; k8 < 4; ++k8) {
            uint32_t a[4][4], b[4][2];
            #pragma unroll
            for (int mt = 0; mt < 4; ++mt) {
                uint32_t ad = ab + swz((uint32_t)(
                    (mw + mt * 16 + (q & 1) * 8 + r) * 128 + k8 * 32 + (q >> 1) * 16));
                ldsm4(ad, a[mt][0], a[mt][1], a[mt][2], a[mt][3]);
            }
            #pragma unroll
            for (int p = 0; p < 2; ++p) {
                uint32_t bd = bb + swz((uint32_t)(
                    (nw + p * 16 + (q >> 1) * 8 + r) * 128 + k8 * 32 + (q & 1) * 16));
                ldsm4(bd, b[2 * p][0], b[2 * p][1], b[2 * p + 1][0], b[2 * p + 1][1]);
            }
            #pragma unroll
            for (int mt = 0; mt < 4; ++mt)
                #pragma unroll
                for (int nt = 0; nt < 4; ++nt)
                    mma_tf32(c[mt][nt][0], c[mt][nt][1], c[mt][nt][2], c[mt][nt][3],
                             a[mt][0], a[mt][1], a[mt][2], a[mt][3],
                             b[nt][0], b[nt][1]);
        }

        // ---- stage next chunk into the other buffer ----
        if (ch + 1 < NCH) {
            store_chunk(buf ^ 1);
            __syncthreads();
        }
    }

    // ---- epilogue: direct STG.64 per mma-tile row pair ----
    #pragma unroll
    for (int mt = 0; mt < 4; ++mt) {
        const int m = m0 + mw + mt * 16 + g;
        float* row0 = out + (size_t)m * (Ldim * Ddim) + (size_t)l * Ddim + n0 + nw;
        float* row1 = row0 + (size_t)8 * (Ldim * Ddim);
        #pragma unroll
        for (int nt = 0; nt < 4; ++nt) {
            const int nc = nt * 8 + 2 * tg;
            *(float2*)(row0 + nc) = make_float2(c[mt][nt][0], c[mt][nt][1]);
            *(float2*)(row1 + nc) = make_float2(c[mt][nt][2], c[mt][nt][3]);
        }
    }
}

extern "C" void kernel_launch(void* const* d_in, const int* in_sizes, int n_in,
                              void* d_out, int out_size) {
    const float* code = (const float*)d_in[0];   // [256, 64, 256]
    const float* W    = (const float*)d_in[1];   // [64, 256, 1024]
    float* out        = (float*)d_out;           // [256, 64, 1024]

    cudaFuncSetAttribute(grouped_gemm_tf32,
                         cudaFuncAttributeMaxDynamicSharedMemorySize, SMEM_TOTAL);
    dim3 grid(Ddim / BN, 256 / BM, Ldim);        // (8, 2, 64) = 1024 CTAs
    grouped_gemm_tf32<<<grid, 256, SMEM_TOTAL>>>(code, W, out);
}

// round 9
// speedup vs baseline: 1.4258x; 1.4258x over previous
#include <cuda_runtime.h>
#include <cstdint>

// out[b,l,d] = sum_c code[b,l,c] * W[l,c,d]
// code: [256, 64, 256] f32,  W: [64, 256, 1024] f32,  out: [256, 64, 1024] f32
// Per l: A[M=256,K=256] (row stride 16384) x B[K=256,N=1024] -> [M,N]
// tf32 mma.sync GEMM (base sm_103 ISA — tcgen05 is not compilable in this
// harness: it lowers via compute_103 without the 'a' feature suffix).
// CTA 128x128, BK=32, 8 warps (2M x 4N), warp tile 64x32, m16n8k8 tf32.

static constexpr int Ldim = 64, Cdim = 256, Ddim = 1024;
static constexpr int BM = 128, BN = 128, BK = 32;
static constexpr int NCH = Cdim / BK;                 // 8
static constexpr int SMEM_TOTAL = 2 * (BM * BK + BN * BK) * 4;   // 65536

__device__ __forceinline__ uint32_t swz(uint32_t o) { return o ^ ((o >> 3) & 0x70); }
__device__ __forceinline__ uint32_t smem_u32(const void* p) {
    uint32_t a;
    asm("{ .reg .u64 t; cvta.to.shared.u64 t, %1; cvt.u32.u64 %0, t; }" : "=r"(a) : "l"(p));
    return a;
}
__device__ __forceinline__ uint32_t f2tf(float f) {
    uint32_t r;
    asm("cvt.rna.tf32.f32 %0, %1;" : "=r"(r) : "f"(f));
    return r;
}
__device__ __forceinline__ void sts128(uint32_t addr, uint32_t x, uint32_t y,
                                       uint32_t z, uint32_t w) {
    asm volatile("st.shared.v4.b32 [%0], {%1, %2, %3, %4};"
                 :: "r"(addr), "r"(x), "r"(y), "r"(z), "r"(w) : "memory");
}
__device__ __forceinline__ void ldsm4(uint32_t addr, uint32_t& r0, uint32_t& r1,
                                      uint32_t& r2, uint32_t& r3) {
    asm volatile("ldmatrix.sync.aligned.m8n8.x4.shared.b16 {%0, %1, %2, %3}, [%4];"
                 : "=r"(r0), "=r"(r1), "=r"(r2), "=r"(r3) : "r"(addr));
}
__device__ __forceinline__ void mma_tf32(float& c0, float& c1, float& c2, float& c3,
                                         uint32_t a0, uint32_t a1, uint32_t a2, uint32_t a3,
                                         uint32_t b0, uint32_t b1) {
    asm volatile(
        "mma.sync.aligned.m16n8k8.row.col.f32.tf32.tf32.f32 "
        "{%0, %1, %2, %3}, {%4, %5, %6, %7}, {%8, %9}, {%0, %1, %2, %3};"
        : "+f"(c0), "+f"(c1), "+f"(c2), "+f"(c3)
        : "r"(a0), "r"(a1), "r"(a2), "r"(a3), "r"(b0), "r"(b1));
}

extern "C" __global__ void __launch_bounds__(256, 1)
grouped_gemm_tf32(const float* __restrict__ code,
                  const float* __restrict__ W,
                  float* __restrict__ out) {
    extern __shared__ char smem[];
    const uint32_t sbase = smem_u32(smem);

    const int tid  = threadIdx.x;
    const int lane = tid & 31;
    const int wid  = tid >> 5;
    const int l  = blockIdx.z;
    const int m0 = blockIdx.y * BM;
    const int n0 = blockIdx.x * BN;

    const int mw = (wid >> 2) * 64;    // warp M offset within CTA tile
    const int nw = (wid & 3) * 32;     // warp N offset
    const int q  = lane >> 3;          // ldmatrix quadrant
    const int r  = lane & 7;
    const int g  = lane >> 2;          // mma group id
    const int tg = lane & 3;           // thread in group

    // Global-load assignments
    const int arow = tid >> 1;                 // 0..127  (M row)
    const int acol = (tid & 1) * 16;           // k offset (16 floats per thread)
    const int bn   = tid & 127;                // N column
    const int bk   = (tid >> 7) * 16;          // k offset (16 rows per thread)

    const float* Ag = code + (size_t)l * Cdim
                      + (size_t)(m0 + arow) * (Ldim * Cdim) + acol;
    const float* Bg = W + (size_t)l * Cdim * Ddim + (size_t)bk * Ddim + n0 + bn;

    float c[4][4][4];
    #pragma unroll
    for (int i = 0; i < 4; i++)
        #pragma unroll
        for (int j = 0; j < 4; j++)
            #pragma unroll
            for (int k = 0; k < 4; k++)
                c[i][j][k] = 0.f;

    float4 as[4];
    float  bs[16];

    // ---- prologue: load chunk 0 ----
    #pragma unroll
    for (int j = 0; j < 4; j++) as[j] = *(const float4*)(Ag + 4 * j);
    #pragma unroll
    for (int j = 0; j < 16; j++) bs[j] = Bg[(size_t)j * Ddim];

    // store chunk into buffer `buf` with fp32->tf32 rounding
    auto store_chunk = [&](int buf) {
        const uint32_t ab = sbase + buf * ((BM + BN) * BK * 4);
        const uint32_t bb = ab + BM * BK * 4;
        #pragma unroll
        for (int j = 0; j < 4; j++) {
            uint32_t o = swz((uint32_t)(arow * 128 + (acol + 4 * j) * 4));
            sts128(ab + o, f2tf(as[j].x), f2tf(as[j].y), f2tf(as[j].z), f2tf(as[j].w));
        }
        #pragma unroll
        for (int jj = 0; jj < 4; jj++) {
            uint32_t o = swz((uint32_t)(bn * 128 + (bk + 4 * jj) * 4));
            sts128(bb + o, f2tf(bs[4 * jj + 0]), f2tf(bs[4 * jj + 1]),
                           f2tf(bs[4 * jj + 2]), f2tf(bs[4 * jj + 3]));
        }
    };

    store_chunk(0);
    __syncthreads();

    for (int ch = 0; ch < NCH; ++ch) {
        const int buf = ch & 1;

        // prefetch next chunk's globals into registers (overlaps with mma)
        if (ch + 1 < NCH) {
            const float* Agn = Ag + (ch + 1) * BK;
            const float* Bgn = Bg + (size_t)(ch + 1) * BK * Ddim;
            #pragma unroll
            for (int j = 0; j < 4; j++) as[j] = *(const float4*)(Agn + 4 * j);
            #pragma unroll
            for (int j = 0; j < 16; j++) bs[j] = Bgn[(size_t)j * Ddim];
        }

        // ---- compute this chunk ----
        const uint32_t ab = sbase + buf * ((BM + BN) * BK * 4);
        const uint32_t bb = ab + BM * BK * 4;
        #pragma unroll
        for (int k8 = 0; k8 < 4; ++k8) {
            uint32_t a[4][4], b[4][2];
            #pragma unroll
            for (int mt = 0; mt < 4; ++mt) {
                uint32_t ad = ab + swz((uint32_t)(
                    (mw + mt * 16 + (q & 1) * 8 + r) * 128 + k8 * 32 + (q >> 1) * 16));
                ldsm4(ad, a[mt][0], a[mt][1], a[mt][2], a[mt][3]);
            }
            #pragma unroll
            for (int p = 0; p < 2; ++p) {
                uint32_t bd = bb + swz((uint32_t)(
                    (nw + p * 16 + (q >> 1) * 8 + r) * 128 + k8 * 32 + (q & 1) * 16));
                ldsm4(bd, b[2 * p][0], b[2 * p][1], b[2 * p + 1][0], b[2 * p + 1][1]);
            }
            #pragma unroll
            for (int mt = 0; mt < 4; ++mt)
                #pragma unroll
                for (int nt = 0; nt < 4; ++nt)
                    mma_tf32(c[mt][nt][0], c[mt][nt][1], c[mt][nt][2], c[mt][nt][3],
                             a[mt][0], a[mt][1], a[mt][2], a[mt][3],
                             b[nt][0], b[nt][1]);
        }

        // ---- stage next chunk into the other buffer ----
        if (ch + 1 < NCH) {
            store_chunk(buf ^ 1);
            __syncthreads();
        }
    }

    // ---- epilogue: direct STG.64 per mma-tile row pair ----
    #pragma unroll
    for (int mt = 0; mt < 4; ++mt) {
        const int m = m0 + mw + mt * 16 + g;
        float* row0 = out + (size_t)m * (Ldim * Ddim) + (size_t)l * Ddim + n0 + nw;
        float* row1 = row0 + (size_t)8 * (Ldim * Ddim);
        #pragma unroll
        for (int nt = 0; nt < 4; ++nt) {
            const int nc = nt * 8 + 2 * tg;
            *(float2*)(row0 + nc) = make_float2(c[mt][nt][0], c[mt][nt][1]);
            *(float2*)(row1 + nc) = make_float2(c[mt][nt][2], c[mt][nt][3]);
        }
    }
}

extern "C" void kernel_launch(void* const* d_in, const int* in_sizes, int n_in,
                              void* d_out, int out_size) {
    const float* code = (const float*)d_in[0];   // [256, 64, 256]
    const float* W    = (const float*)d_in[1];   // [64, 256, 1024]
    float* out        = (float*)d_out;           // [256, 64, 1024]

    cudaFuncSetAttribute(grouped_gemm_tf32,
                         cudaFuncAttributeMaxDynamicSharedMemorySize, SMEM_TOTAL);
    dim3 grid(Ddim / BN, 256 / BM, Ldim);        // (8, 2, 64) = 1024 CTAs
    grouped_gemm_tf32<<<grid, 256, SMEM_TOTAL>>>(code, W, out);
}

// round 10
// speedup vs baseline: 1.4316x; 1.0041x over previous
#include <cuda_runtime.h>
#include <cstdint>

// out[b,l,d] = sum_c code[b,l,c] * W[l,c,d]
// code: [256, 64, 256] f32,  W: [64, 256, 1024] f32,  out: [256, 64, 1024] f32
// Per l: A[M=256,K=256] (row stride 16384) x B[K=256,N=1024] -> [M,N]
// tf32 mma.sync GEMM (base sm_103 ISA — tcgen05 is not compilable in this
// harness: it lowers via compute_103 without the 'a' feature suffix).
// CTA 128x128, BK=32, 8 warps (2M x 4N), warp tile 64x32, m16n8k8 tf32.

static constexpr int Ldim = 64, Cdim = 256, Ddim = 1024;
static constexpr int BM = 128, BN = 128, BK = 32;
static constexpr int NCH = Cdim / BK;                 // 8
static constexpr int SMEM_TOTAL = 2 * (BM * BK + BN * BK) * 4;   // 65536

__device__ __forceinline__ uint32_t swz(uint32_t o) { return o ^ ((o >> 3) & 0x70); }
__device__ __forceinline__ uint32_t smem_u32(const void* p) {
    uint32_t a;
    asm("{ .reg .u64 t; cvta.to.shared.u64 t, %1; cvt.u32.u64 %0, t; }" : "=r"(a) : "l"(p));
    return a;
}
__device__ __forceinline__ uint32_t f2tf(float f) {
    uint32_t r;
    asm("cvt.rna.tf32.f32 %0, %1;" : "=r"(r) : "f"(f));
    return r;
}
__device__ __forceinline__ void sts128(uint32_t addr, uint32_t x, uint32_t y,
                                       uint32_t z, uint32_t w) {
    asm volatile("st.shared.v4.b32 [%0], {%1, %2, %3, %4};"
                 :: "r"(addr), "r"(x), "r"(y), "r"(z), "r"(w) : "memory");
}
__device__ __forceinline__ void ldsm4(uint32_t addr, uint32_t& r0, uint32_t& r1,
                                      uint32_t& r2, uint32_t& r3) {
    asm volatile("ldmatrix.sync.aligned.m8n8.x4.shared.b16 {%0, %1, %2, %3}, [%4];"
                 : "=r"(r0), "=r"(r1), "=r"(r2), "=r"(r3) : "r"(addr));
}
__device__ __forceinline__ void mma_tf32(float& c0, float& c1, float& c2, float& c3,
                                         uint32_t a0, uint32_t a1, uint32_t a2, uint32_t a3,
                                         uint32_t b0, uint32_t b1) {
    asm volatile(
        "mma.sync.aligned.m16n8k8.row.col.f32.tf32.tf32.f32 "
        "{%0, %1, %2, %3}, {%4, %5, %6, %7}, {%8, %9}, {%0, %1, %2, %3};"
        : "+f"(c0), "+f"(c1), "+f"(c2), "+f"(c3)
        : "r"(a0), "r"(a1), "r"(a2), "r"(a3), "r"(b0), "r"(b1));
}

extern "C" __global__ void __launch_bounds__(256, 1)
grouped_gemm_tf32(const float* __restrict__ code,
                  const float* __restrict__ W,
                  float* __restrict__ out) {
    extern __shared__ char smem[];
    const uint32_t sbase = smem_u32(smem);

    const int tid  = threadIdx.x;
    const int lane = tid & 31;
    const int wid  = tid >> 5;
    const int l  = blockIdx.z;
    const int m0 = blockIdx.y * BM;
    const int n0 = blockIdx.x * BN;

    const int mw = (wid >> 2) * 64;    // warp M offset within CTA tile
    const int nw = (wid & 3) * 32;     // warp N offset
    const int q  = lane >> 3;          // ldmatrix quadrant
    const int r  = lane & 7;
    const int g  = lane >> 2;          // mma group id
    const int tg = lane & 3;           // thread in group

    // Global-load assignments
    const int arow = tid >> 1;                 // 0..127  (M row)
    const int acol = (tid & 1) * 16;           // k offset (16 floats per thread)
    const int bn   = tid & 127;                // N column
    const int bk   = (tid >> 7) * 16;          // k offset (16 rows per thread)

    const float* Ag = code + (size_t)l * Cdim
                      + (size_t)(m0 + arow) * (Ldim * Cdim) + acol;
    const float* Bg = W + (size_t)l * Cdim * Ddim + (size_t)bk * Ddim + n0 + bn;

    float c[4][4][4];
    #pragma unroll
    for (int i = 0; i < 4; i++)
        #pragma unroll
        for (int j = 0; j < 4; j++)
            #pragma unroll
            for (int k = 0; k < 4; k++)
                c[i][j][k] = 0.f;

    float4 as[4];
    float  bs[16];

    // ---- prologue: load chunk 0 ----
    #pragma unroll
    for (int j = 0; j < 4; j++) as[j] = *(const float4*)(Ag + 4 * j);
    #pragma unroll
    for (int j = 0; j < 16; j++) bs[j] = Bg[(size_t)j * Ddim];

    // store chunk into buffer `buf` with fp32->tf32 rounding
    auto store_chunk = [&](int buf) {
        const uint32_t ab = sbase + buf * ((BM + BN) * BK * 4);
        const uint32_t bb = ab + BM * BK * 4;
        #pragma unroll
        for (int j = 0; j < 4; j++) {
            uint32_t o = swz((uint32_t)(arow * 128 + (acol + 4 * j) * 4));
            sts128(ab + o, f2tf(as[j].x), f2tf(as[j].y), f2tf(as[j].z), f2tf(as[j].w));
        }
        #pragma unroll
        for (int jj = 0; jj < 4; jj++) {
            uint32_t o = swz((uint32_t)(bn * 128 + (bk + 4 * jj) * 4));
            sts128(bb + o, f2tf(bs[4 * jj + 0]), f2tf(bs[4 * jj + 1]),
                           f2tf(bs[4 * jj + 2]), f2tf(bs[4 * jj + 3]));
        }
    };

    store_chunk(0);
    __syncthreads();

    for (int ch = 0; ch < NCH; ++ch) {
        const int buf = ch & 1;

        // prefetch next chunk's globals into registers (overlaps with mma)
        if (ch + 1 < NCH) {
            const float* Agn = Ag + (ch + 1) * BK;
            const float* Bgn = Bg + (size_t)(ch + 1) * BK * Ddim;
            #pragma unroll
            for (int j = 0; j < 4; j++) as[j] = *(const float4*)(Agn + 4 * j);
            #pragma unroll
            for (int j = 0; j < 16; j++) bs[j] = Bgn[(size_t)j * Ddim];
        }

        // ---- compute this chunk ----
        const uint32_t ab = sbase + buf * ((BM + BN) * BK * 4);
        const uint32_t bb = ab + BM * BK * 4;
        #pragma unroll
        for (int k8 = 0; k8 < 4; ++k8) {
            uint32_t a[4][4], b[4][2];
            #pragma unroll
            for (int mt = 0; mt < 4; ++mt) {
                uint32_t ad = ab + swz((uint32_t)(
                    (mw + mt * 16 + (q & 1) * 8 + r) * 128 + k8 * 32 + (q >> 1) * 16));
                ldsm4(ad, a[mt][0], a[mt][1], a[mt][2], a[mt][3]);
            }
            #pragma unroll
            for (int p = 0; p < 2; ++p) {
                uint32_t bd = bb + swz((uint32_t)(
                    (nw + p * 16 + (q >> 1) * 8 + r) * 128 + k8 * 32 + (q & 1) * 16));
                ldsm4(bd, b[2 * p][0], b[2 * p][1], b[2 * p + 1][0], b[2 * p + 1][1]);
            }
            #pragma unroll
            for (int mt = 0; mt < 4; ++mt)
                #pragma unroll
                for (int nt = 0; nt < 4; ++nt)
                    mma_tf32(c[mt][nt][0], c[mt][nt][1], c[mt][nt][2], c[mt][nt][3],
                             a[mt][0], a[mt][1], a[mt][2], a[mt][3],
                             b[nt][0], b[nt][1]);
        }

        // ---- stage next chunk into the other buffer ----
        if (ch + 1 < NCH) {
            store_chunk(buf ^ 1);
            __syncthreads();
        }
    }

    // ---- epilogue: direct STG.64 per mma-tile row pair ----
    #pragma unroll
    for (int mt = 0; mt < 4; ++mt) {
        const int m = m0 + mw + mt * 16 + g;
        float* row0 = out + (size_t)m * (Ldim * Ddim) + (size_t)l * Ddim + n0 + nw;
        float* row1 = row0 + (size_t)8 * (Ldim * Ddim);
        #pragma unroll
        for (int nt = 0; nt < 4; ++nt) {
            const int nc = nt * 8 + 2 * tg;
            *(float2*)(row0 + nc) = make_float2(c[mt][nt][0], c[mt][nt][1]);
            *(float2*)(row1 + nc) = make_float2(c[mt][nt][2], c[mt][nt][3]);
        }
    }
}

extern "C" void kernel_launch(void* const* d_in, const int* in_sizes, int n_in,
                              void* d_out, int out_size) {
    const float* code = (const float*)d_in[0];   // [256, 64, 256]
    const float* W    = (const float*)d_in[1];   // [64, 256, 1024]
    float* out        = (float*)d_out;           // [256, 64, 1024]

    cudaFuncSetAttribute(grouped_gemm_tf32,
                         cudaFuncAttributeMaxDynamicSharedMemorySize, SMEM_TOTAL);
    dim3 grid(Ddim / BN, 256 / BM, Ldim);        // (8, 2, 64) = 1024 CTAs
    grouped_gemm_tf32<<<grid, 256, SMEM_TOTAL>>>(code, W, out);
}

// round 12
// speedup vs baseline: 1.7098x; 1.1943x over previous
#include <cuda_runtime.h>
#include <cstdint>

// out[b,l,d] = sum_c code[b,l,c] * W[l,c,d]
// code: [256, 64, 256] f32,  W: [64, 256, 1024] f32,  out: [256, 64, 1024] f32
// Per l: A[M=256,K=256] (row stride 16384) x B[K=256,N=1024] -> [M,N]
// tf32 mma.sync GEMM. CTA 128x128, BK=32, 8 warps (2M x 4N), warp tile 64x32.
// R12: A tile staged with cp.async (raw fp32, converted to tf32 post-ldmatrix);
// B tile register-transposed with cvt.rna at STS. Live regs ~120 so
// __launch_bounds__(256,2) gives true 2-CTA/SM co-residency.

static constexpr int Ldim = 64, Cdim = 256, Ddim = 1024;
static constexpr int BM = 128, BN = 128, BK = 32;
static constexpr int NCH = Cdim / BK;                 // 8
static constexpr int SMEM_TOTAL = 2 * (BM * BK + BN * BK) * 4;   // 65536

__device__ __forceinline__ uint32_t swz(uint32_t o) { return o ^ ((o >> 3) & 0x70); }
__device__ __forceinline__ uint32_t smem_u32(const void* p) {
    uint32_t a;
    asm("{ .reg .u64 t; cvta.to.shared.u64 t, %1; cvt.u32.u64 %0, t; }" : "=r"(a) : "l"(p));
    return a;
}
__device__ __forceinline__ uint32_t f2tf(float f) {
    uint32_t r;
    asm("cvt.rna.tf32.f32 %0, %1;" : "=r"(r) : "f"(f));
    return r;
}
__device__ __forceinline__ uint32_t u2tf(uint32_t u) {
    return f2tf(__uint_as_float(u));
}
__device__ __forceinline__ void sts128(uint32_t addr, uint32_t x, uint32_t y,
                                       uint32_t z, uint32_t w) {
    asm volatile("st.shared.v4.b32 [%0], {%1, %2, %3, %4};"
                 :: "r"(addr), "r"(x), "r"(y), "r"(z), "r"(w) : "memory");
}
__device__ __forceinline__ void cpasync16(uint32_t dst, const void* src) {
    asm volatile("cp.async.ca.shared.global [%0], [%1], 16;"
                 :: "r"(dst), "l"(src) : "memory");
}
__device__ __forceinline__ void ldsm4(uint32_t addr, uint32_t& r0, uint32_t& r1,
                                      uint32_t& r2, uint32_t& r3) {
    asm volatile("ldmatrix.sync.aligned.m8n8.x4.shared.b16 {%0, %1, %2, %3}, [%4];"
                 : "=r"(r0), "=r"(r1), "=r"(r2), "=r"(r3) : "r"(addr));
}
__device__ __forceinline__ void mma_tf32(float& c0, float& c1, float& c2, float& c3,
                                         uint32_t a0, uint32_t a1, uint32_t a2, uint32_t a3,
                                         uint32_t b0, uint32_t b1) {
    asm volatile(
        "mma.sync.aligned.m16n8k8.row.col.f32.tf32.tf32.f32 "
        "{%0, %1, %2, %3}, {%4, %5, %6, %7}, {%8, %9}, {%0, %1, %2, %3};"
        : "+f"(c0), "+f"(c1), "+f"(c2), "+f"(c3)
        : "r"(a0), "r"(a1), "r"(a2), "r"(a3), "r"(b0), "r"(b1));
}

extern "C" __global__ void __launch_bounds__(256, 2)
grouped_gemm_tf32(const float* __restrict__ code,
                  const float* __restrict__ W,
                  float* __restrict__ out) {
    extern __shared__ char smem[];
    const uint32_t sbase = smem_u32(smem);

    const int tid  = threadIdx.x;
    const int lane = tid & 31;
    const int wid  = tid >> 5;
    const int l  = blockIdx.z;
    const int m0 = blockIdx.y * BM;
    const int n0 = blockIdx.x * BN;

    const int mw = (wid >> 2) * 64;    // warp M offset within CTA tile
    const int nw = (wid & 3) * 32;     // warp N offset
    const int q  = lane >> 3;          // ldmatrix quadrant
    const int r  = lane & 7;
    const int g  = lane >> 2;          // mma group id
    const int tg = lane & 3;           // thread in group

    // Global-load assignments
    const int arow = tid >> 1;                 // 0..127  (M row)
    const int acol = (tid & 1) * 16;           // k offset (16 floats per thread)
    const int bn   = tid & 127;                // N column
    const int bk   = (tid >> 7) * 16;          // k offset (16 rows per thread)

    const float* Ag = code + (size_t)l * Cdim
                      + (size_t)(m0 + arow) * (Ldim * Cdim) + acol;
    const float* Bg = W + (size_t)l * Cdim * Ddim + (size_t)bk * Ddim + n0 + bn;

    float c[4][4][4];
    #pragma unroll
    for (int i = 0; i < 4; i++)
        #pragma unroll
        for (int j = 0; j < 4; j++)
            #pragma unroll
            for (int k = 0; k < 4; k++)
                c[i][j][k] = 0.f;

    float bs[16];   // B register staging only (A goes via cp.async)

    // issue cp.async for A chunk `ch` into buffer `buf`
    auto issue_A = [&](int ch, int buf) {
        const uint32_t ab = sbase + buf * ((BM + BN) * BK * 4);
        const float* Agc = Ag + ch * BK;
        #pragma unroll
        for (int j = 0; j < 4; j++) {
            uint32_t o = swz((uint32_t)(arow * 128 + (acol + 4 * j) * 4));
            cpasync16(ab + o, Agc + 4 * j);
        }
        asm volatile("cp.async.commit_group;" ::: "memory");
    };
    // store B chunk (already in bs[]) into buffer `buf` with tf32 rounding
    auto store_B = [&](int buf) {
        const uint32_t bb = sbase + buf * ((BM + BN) * BK * 4) + BM * BK * 4;
        #pragma unroll
        for (int jj = 0; jj < 4; jj++) {
            uint32_t o = swz((uint32_t)(bn * 128 + (bk + 4 * jj) * 4));
            sts128(bb + o, f2tf(bs[4 * jj + 0]), f2tf(bs[4 * jj + 1]),
                           f2tf(bs[4 * jj + 2]), f2tf(bs[4 * jj + 3]));
        }
    };

    // ---- prologue: stage chunk 0 ----
    issue_A(0, 0);
    #pragma unroll
    for (int j = 0; j < 16; j++) bs[j] = Bg[(size_t)j * Ddim];
    store_B(0);
    asm volatile("cp.async.wait_group 0;" ::: "memory");
    __syncthreads();

    for (int ch = 0; ch < NCH; ++ch) {
        const int buf = ch & 1;

        // stage next chunk: A via cp.async, B via register prefetch
        if (ch + 1 < NCH) {
            issue_A(ch + 1, buf ^ 1);
            const float* Bgn = Bg + (size_t)(ch + 1) * BK * Ddim;
            #pragma unroll
            for (int j = 0; j < 16; j++) bs[j] = Bgn[(size_t)j * Ddim];
        }

        // ---- compute this chunk ----
        const uint32_t ab = sbase + buf * ((BM + BN) * BK * 4);
        const uint32_t bb = ab + BM * BK * 4;
        #pragma unroll
        for (int k8 = 0; k8 < 4; ++k8) {
            uint32_t a[4][4], b[4][2];
            #pragma unroll
            for (int mt = 0; mt < 4; ++mt) {
                uint32_t ad = ab + swz((uint32_t)(
                    (mw + mt * 16 + (q & 1) * 8 + r) * 128 + k8 * 32 + (q >> 1) * 16));
                ldsm4(ad, a[mt][0], a[mt][1], a[mt][2], a[mt][3]);
                // A was staged raw fp32 -> round fragments to tf32 here
                a[mt][0] = u2tf(a[mt][0]);
                a[mt][1] = u2tf(a[mt][1]);
                a[mt][2] = u2tf(a[mt][2]);
                a[mt][3] = u2tf(a[mt][3]);
            }
            #pragma unroll
            for (int p = 0; p < 2; ++p) {
                uint32_t bd = bb + swz((uint32_t)(
                    (nw + p * 16 + (q >> 1) * 8 + r) * 128 + k8 * 32 + (q & 1) * 16));
                ldsm4(bd, b[2 * p][0], b[2 * p][1], b[2 * p + 1][0], b[2 * p + 1][1]);
            }
            #pragma unroll
            for (int mt = 0; mt < 4; ++mt)
                #pragma unroll
                for (int nt = 0; nt < 4; ++nt)
                    mma_tf32(c[mt][nt][0], c[mt][nt][1], c[mt][nt][2], c[mt][nt][3],
                             a[mt][0], a[mt][1], a[mt][2], a[mt][3],
                             b[nt][0], b[nt][1]);
        }

        // ---- finish staging next chunk ----
        if (ch + 1 < NCH) {
            store_B(buf ^ 1);
            asm volatile("cp.async.wait_group 0;" ::: "memory");
            __syncthreads();
        }
    }

    // ---- epilogue: direct STG.64 per mma-tile row pair ----
    #pragma unroll
    for (int mt = 0; mt < 4; ++mt) {
        const int m = m0 + mw + mt * 16 + g;
        float* row0 = out + (size_t)m * (Ldim * Ddim) + (size_t)l * Ddim + n0 + nw;
        float* row1 = row0 + (size_t)8 * (Ldim * Ddim);
        #pragma unroll
        for (int nt = 0; nt < 4; ++nt) {
            const int nc = nt * 8 + 2 * tg;
            *(float2*)(row0 + nc) = make_float2(c[mt][nt][0], c[mt][nt][1]);
            *(float2*)(row1 + nc) = make_float2(c[mt][nt][2], c[mt][nt][3]);
        }
    }
}

extern "C" void kernel_launch(void* const* d_in, const int* in_sizes, int n_in,
                              void* d_out, int out_size) {
    const float* code = (const float*)d_in[0];   // [256, 64, 256]
    const float* W    = (const float*)d_in[1];   // [64, 256, 1024]
    float* out        = (float*)d_out;           // [256, 64, 1024]

    cudaFuncSetAttribute(grouped_gemm_tf32,
                         cudaFuncAttributeMaxDynamicSharedMemorySize, SMEM_TOTAL);
    dim3 grid(Ddim / BN, 256 / BM, Ldim);        // (8, 2, 64) = 1024 CTAs
    grouped_gemm_tf32<<<grid, 256, SMEM_TOTAL>>>(code, W, out);
}